// round 6
// baseline (speedup 1.0000x reference)
#include <cuda_runtime.h>
#include <cuda_fp16.h>

#define NN   50000
#define EE   800000
#define DIN  128
#define HH   64
#define AB   6250                 // agg blocks: 8 rows x 6250 = 50000 exactly
#define CAP  (EE + 4 * NN)        // padded CSR capacity (1,000,000; mult of 4)

// ---------------- scratch (static device globals: no allocation) -------------
__device__ int    g_deg[NN];
__device__ int2   g_row[NN];                 // (rowstart, real deg)
__device__ int    g_tot;
__device__ float  g_dinv[NN];
__device__ int    g_rank[EE];                // edge rank within dst segment
__device__ int    g_col[CAP];                // src per CSR slot; pads = NN (dummy)
__device__ __align__(16) __half g_hH[(size_t)(NN + 1) * HH]; // h' = dinv*h (fp16); row NN = 0
__device__ __align__(16) float  g_hA[(size_t)NN * HH];       // agg out, fp32
__device__ float2 g_psT[32 * AB];            // pool sum partials [lanecol][blk]
__device__ float2 g_pmT[32 * AB];            // pool max partials
__device__ float  g_poolS[HH];
__device__ float  g_poolM[HH];

typedef unsigned long long u64;

__device__ __forceinline__ void ffma2(u64& d, u64 a, u64 b) {
    asm("fma.rn.f32x2 %0, %1, %2, %0;" : "+l"(d) : "l"(a), "l"(b));
}
__device__ __forceinline__ u64 pack2(float lo, float hi) {
    u64 r; asm("mov.b64 %0, {%1, %2};" : "=l"(r) : "f"(lo), "f"(hi)); return r;
}
__device__ __forceinline__ void unpack2(float& lo, float& hi, u64 v) {
    asm("mov.b64 {%0, %1}, %2;" : "=f"(lo), "=f"(hi) : "l"(v));
}

// ---------------- setup kernels ----------------------------------------------
// zero deg/tot/dummy-row; fill g_col with NN so pad slots gather zeros
__global__ void init_kernel() {
    int i = blockIdx.x * blockDim.x + threadIdx.x;
    if (i < NN) g_deg[i] = 0;
    if (i == 0) g_tot = 0;
    if (i < 8) reinterpret_cast<int4*>(g_hH + (size_t)NN * HH)[i] = make_int4(0, 0, 0, 0);
    if (i < CAP / 4) reinterpret_cast<int4*>(g_col)[i] = make_int4(NN, NN, NN, NN);
}

// histogram; atomic return value doubles as the edge's rank within its segment
__global__ void count_kernel(const int* __restrict__ ei) {
    int i = blockIdx.x * blockDim.x + threadIdx.x;
    if (i >= EE / 4) return;
    int4 d4 = reinterpret_cast<const int4*>(ei + EE)[i];
    int4 r4;
    r4.x = atomicAdd(&g_deg[d4.x], 1);
    r4.y = atomicAdd(&g_deg[d4.y], 1);
    r4.z = atomicAdd(&g_deg[d4.z], 1);
    r4.w = atomicAdd(&g_deg[d4.w], 1);
    reinterpret_cast<int4*>(g_rank)[i] = r4;
}

// warp-aggregated segment allocator (pads each segment to a multiple of 4) + dinv
__global__ void alloc_kernel() {
    int i    = blockIdx.x * blockDim.x + threadIdx.x;
    int lane = threadIdx.x & 31;
    int d    = (i < NN) ? g_deg[i] : 0;
    int pd   = (d + 3) & ~3;

    int x = pd;
#pragma unroll
    for (int off = 1; off < 32; off <<= 1) {
        int v = __shfl_up_sync(0xFFFFFFFFu, x, off);
        if (lane >= off) x += v;
    }
    int wsum = __shfl_sync(0xFFFFFFFFu, x, 31);
    int base = 0;
    if (lane == 31) base = atomicAdd(&g_tot, wsum);
    base = __shfl_sync(0xFFFFFFFFu, base, 31);

    if (i < NN) {
        g_row[i]  = make_int2(base + x - pd, d);
        g_dinv[i] = rsqrtf((float)d + 1.0f);
    }
}

// atomic-free scatter: slot = rowstart[dst] + rank[e]
__global__ void scatter_kernel(const int* __restrict__ ei) {
    int i = blockIdx.x * blockDim.x + threadIdx.x;
    if (i >= EE / 4) return;
    int4 s4 = reinterpret_cast<const int4*>(ei)[i];
    int4 d4 = reinterpret_cast<const int4*>(ei + EE)[i];
    int4 r4 = reinterpret_cast<const int4*>(g_rank)[i];
    g_col[g_row[d4.x].x + r4.x] = s4.x;
    g_col[g_row[d4.y].x + r4.y] = s4.y;
    g_col[g_row[d4.z].x + r4.z] = s4.z;
    g_col[g_row[d4.w].x + r4.w] = s4.w;
}

// ---------------- GEMM: hH[N,64] = fp16( dinv[i] * (X[N,K] @ W[K,64]) ) ------
// register tile: 4 rows x 32 cols per thread. Column half is WARP-UNIFORM
// (c2 = tid>>6) so the W smem reads are conflict-free broadcasts.
// Per k: 4 LDS.128 + 64 ffma2  ->  f32x2-pipe bound.
template <int K>
__global__ __launch_bounds__(128) void gemm_kernel(const float* __restrict__ X,
                                                   const float* __restrict__ W,
                                                   int nrows) {
    __shared__ float Wsm[K * 64];
    for (int i = threadIdx.x; i < K * 16; i += 128)
        reinterpret_cast<float4*>(Wsm)[i] = reinterpret_cast<const float4*>(W)[i];
    __syncthreads();

    const int c2 = threadIdx.x >> 6;          // 0/1: cols 0-31 / 32-63 (warp-uniform)
    const int rq = threadIdx.x & 63;
    const int r0 = blockIdx.x * 256 + rq * 4; // 4 consecutive rows per thread

    u64 acc[4][16];
#pragma unroll
    for (int r = 0; r < 4; r++)
#pragma unroll
        for (int c = 0; c < 16; c++) acc[r][c] = 0ull;

    const float4* xp = reinterpret_cast<const float4*>(X);
    const bool rv[4] = { r0 < nrows, r0 + 1 < nrows, r0 + 2 < nrows, r0 + 3 < nrows };

#pragma unroll 1
    for (int kc = 0; kc < K / 4; kc++) {
        float4 xv[4];
#pragma unroll
        for (int r = 0; r < 4; r++)
            xv[r] = rv[r] ? xp[(size_t)(r0 + r) * (K / 4) + kc]
                          : make_float4(0.f, 0.f, 0.f, 0.f);
#pragma unroll
        for (int q = 0; q < 4; q++) {
            const int k = kc * 4 + q;
            const ulonglong2* wr =
                reinterpret_cast<const ulonglong2*>(Wsm + k * 64 + c2 * 32);
            u64 w[8];
#pragma unroll
            for (int j = 0; j < 4; j++) {
                ulonglong2 t = wr[j];
                w[2 * j] = t.x; w[2 * j + 1] = t.y;
            }
            const float xs0 = (q == 0) ? xv[0].x : (q == 1) ? xv[0].y : (q == 2) ? xv[0].z : xv[0].w;
            const float xs1 = (q == 0) ? xv[1].x : (q == 1) ? xv[1].y : (q == 2) ? xv[1].z : xv[1].w;
            const float xs2 = (q == 0) ? xv[2].x : (q == 1) ? xv[2].y : (q == 2) ? xv[2].z : xv[2].w;
            const float xs3 = (q == 0) ? xv[3].x : (q == 1) ? xv[3].y : (q == 2) ? xv[3].z : xv[3].w;
            const u64 s0 = pack2(xs0, xs0), s1 = pack2(xs1, xs1);
            const u64 s2 = pack2(xs2, xs2), s3 = pack2(xs3, xs3);
#pragma unroll
            for (int c = 0; c < 8; c++) {
                ffma2(acc[0][2 * c],     s0, w[c]);
                ffma2(acc[1][2 * c],     s1, w[c]);
                ffma2(acc[2][2 * c],     s2, w[c]);
                ffma2(acc[3][2 * c],     s3, w[c]);
                // second u64 of the 16 cols handled via c index mapping below
            }
#pragma unroll
            for (int c = 0; c < 8; c++) {
                ffma2(acc[0][2 * c + 1], s0, w[c]);   // placeholder overwritten below
            }
        }
    }
    // NOTE: the loop above is wrong-shaped; real implementation below.
}

// ---- The template above is replaced by this correct specialization ----------
template <int K>
__global__ __launch_bounds__(128) void gemm_tile_kernel(const float* __restrict__ X,
                                                        const float* __restrict__ W,
                                                        int nrows) {
    __shared__ float Wsm[K * 64];
    for (int i = threadIdx.x; i < K * 16; i += 128)
        reinterpret_cast<float4*>(Wsm)[i] = reinterpret_cast<const float4*>(W)[i];
    __syncthreads();

    const int c2 = threadIdx.x >> 6;          // warp-uniform column half
    const int rq = threadIdx.x & 63;
    const int r0 = blockIdx.x * 256 + rq * 4;

    u64 acc[4][16];
#pragma unroll
    for (int r = 0; r < 4; r++)
#pragma unroll
        for (int c = 0; c < 16; c++) acc[r][c] = 0ull;

    const float4* xp = reinterpret_cast<const float4*>(X);
    const bool rv1 = (r0 + 1 < nrows), rv2 = (r0 + 2 < nrows), rv3 = (r0 + 3 < nrows);
    if (r0 >= nrows) return;

#pragma unroll 1
    for (int kc = 0; kc < K / 4; kc++) {
        float4 xv0 = xp[(size_t)r0 * (K / 4) + kc];
        float4 xv1 = rv1 ? xp[(size_t)(r0 + 1) * (K / 4) + kc] : make_float4(0.f,0.f,0.f,0.f);
        float4 xv2 = rv2 ? xp[(size_t)(r0 + 2) * (K / 4) + kc] : make_float4(0.f,0.f,0.f,0.f);
        float4 xv3 = rv3 ? xp[(size_t)(r0 + 3) * (K / 4) + kc] : make_float4(0.f,0.f,0.f,0.f);
        const float x0[4] = {xv0.x, xv0.y, xv0.z, xv0.w};
        const float x1[4] = {xv1.x, xv1.y, xv1.z, xv1.w};
        const float x2[4] = {xv2.x, xv2.y, xv2.z, xv2.w};
        const float x3[4] = {xv3.x, xv3.y, xv3.z, xv3.w};
#pragma unroll
        for (int q = 0; q < 4; q++) {
            const int k = kc * 4 + q;
            const ulonglong2* wr =
                reinterpret_cast<const ulonglong2*>(Wsm + k * 64 + c2 * 32);
            u64 w[16 / 2];
            ulonglong2 t0 = wr[0], t1 = wr[1], t2 = wr[2], t3 = wr[3];
            const u64 wv[8] = {t0.x, t0.y, t1.x, t1.y, t2.x, t2.y, t3.x, t3.y};
            (void)w;
            const u64 s0 = pack2(x0[q], x0[q]);
            const u64 s1 = pack2(x1[q], x1[q]);
            const u64 s2 = pack2(x2[q], x2[q]);
            const u64 s3 = pack2(x3[q], x3[q]);
#pragma unroll
            for (int c = 0; c < 8; c++) {
                ffma2(acc[0][c],     s0, wv[c]);
                ffma2(acc[1][c],     s1, wv[c]);
                ffma2(acc[2][c],     s2, wv[c]);
                ffma2(acc[3][c],     s3, wv[c]);
            }
            // cols 16..31 of this half: second 64B of the 128B chunk
            const ulonglong2* wr2 = wr + 4;
            ulonglong2 u0 = wr2[0], u1 = wr2[1], u2 = wr2[2], u3 = wr2[3];
            const u64 wv2[8] = {u0.x, u0.y, u1.x, u1.y, u2.x, u2.y, u3.x, u3.y};
#pragma unroll
            for (int c = 0; c < 8; c++) {
                ffma2(acc[0][8 + c], s0, wv2[c]);
                ffma2(acc[1][8 + c], s1, wv2[c]);
                ffma2(acc[2][8 + c], s2, wv2[c]);
                ffma2(acc[3][8 + c], s3, wv2[c]);
            }
        }
    }

    // epilogue: scale by dinv, cvt fp16, store 64B (this thread's 32 cols)
#pragma unroll
    for (int r = 0; r < 4; r++) {
        int row = r0 + r;
        if (row >= nrows) break;
        float di = g_dinv[row];
        uint4* yp = reinterpret_cast<uint4*>((char*)g_hH + (size_t)row * 128 + c2 * 64);
#pragma unroll
        for (int g = 0; g < 2; g++) {
            unsigned rr[4];
#pragma unroll
            for (int j = 0; j < 4; j++) {
                float lo, hi;
                unpack2(lo, hi, acc[r][g * 8 + 2 * j]);
                float lo2, hi2;
                unpack2(lo2, hi2, acc[r][g * 8 + 2 * j + 1]);
                __half2 hA2 = __floats2half2_rn(lo * di, hi * di);
                __half2 hB2 = __floats2half2_rn(lo2 * di, hi2 * di);
                rr[2 * (j & 1)]     = *reinterpret_cast<unsigned*>(&hA2);
                rr[2 * (j & 1) + 1] = *reinterpret_cast<unsigned*>(&hB2);
                if ((j & 1) == 1) {
                    uint4 o; o.x = rr[0]; o.y = rr[1]; o.z = rr[2]; o.w = rr[3];
                    yp[(g * 2) + (j >> 1)] = o;
                }
            }
        }
    }
}

// ---------------- aggregation: warp per node, shfl-free fp16 gather ----------
__device__ __forceinline__ float2 agg_row(int row, int lane) {
    int2 rd     = g_row[row];
    int  padded = (rd.y + 3) & ~3;
    const int*      cp = g_col + rd.x;
    const unsigned* hb = reinterpret_cast<const unsigned*>(g_hH);

    float ax = 0.f, ay = 0.f;
#pragma unroll 4
    for (int p = 0; p < padded; p++) {
        int sj = __ldg(cp + p);
        unsigned hv = __ldg(hb + sj * 32 + lane);
        float2 f = __half22float2(*reinterpret_cast<__half2*>(&hv));
        ax += f.x;
        ay += f.y;
    }
    return make_float2(ax, ay);
}

__device__ __forceinline__ float2 agg_finish(int row, int lane, float2 a,
                                             const float* bias) {
    const unsigned* hb = reinterpret_cast<const unsigned*>(g_hH);
    unsigned hs = hb[row * 32 + lane];
    float2 fs = __half22float2(*reinterpret_cast<__half2*>(&hs));
    float di = g_dinv[row];
    float2 b = reinterpret_cast<const float2*>(bias)[lane];
    float ox = fmaf(di, a.x + fs.x, b.x);
    float oy = fmaf(di, a.y + fs.y, b.y);
    return make_float2(fmaxf(ox, 0.f), fmaxf(oy, 0.f));
}

__global__ void agg_kernel(const float* __restrict__ bias) {
    int warp = threadIdx.x >> 5;
    int lane = threadIdx.x & 31;
    int row  = blockIdx.x * 8 + warp;
    float2 a = agg_row(row, lane);
    float2 o = agg_finish(row, lane, a, bias);
    reinterpret_cast<float2*>(g_hA)[row * 32 + lane] = o;
}

__global__ void agg_pool_kernel(const float* __restrict__ bias) {
    __shared__ float2 s_sum[8][32];
    __shared__ float2 s_max[8][32];
    int warp = threadIdx.x >> 5;
    int lane = threadIdx.x & 31;
    int row  = blockIdx.x * 8 + warp;

    float2 a = agg_row(row, lane);
    float2 o = agg_finish(row, lane, a, bias);
    s_sum[warp][lane] = o;
    s_max[warp][lane] = o;
    __syncthreads();

    if (threadIdx.x < 32) {
        float2 S = make_float2(0.f, 0.f), M = make_float2(0.f, 0.f);
#pragma unroll
        for (int w = 0; w < 8; w++) {
            float2 v = s_sum[w][threadIdx.x];
            S.x += v.x; S.y += v.y;
            float2 m = s_max[w][threadIdx.x];
            M.x = fmaxf(M.x, m.x); M.y = fmaxf(M.y, m.y);
        }
        g_psT[threadIdx.x * AB + blockIdx.x] = S;
        g_pmT[threadIdx.x * AB + blockIdx.x] = M;
    }
}

__global__ void pool_reduce_kernel() {
    __shared__ float sx[256], sy[256], mx[256], my[256];
    int c   = blockIdx.x;
    int tid = threadIdx.x;
    float ax = 0.f, ay = 0.f, bx = 0.f, by = 0.f;
    for (int i = tid; i < AB; i += 256) {
        float2 s = g_psT[c * AB + i];
        ax += s.x; ay += s.y;
        float2 m = g_pmT[c * AB + i];
        bx = fmaxf(bx, m.x); by = fmaxf(by, m.y);
    }
    sx[tid] = ax; sy[tid] = ay; mx[tid] = bx; my[tid] = by;
    __syncthreads();
    for (int off = 128; off > 0; off >>= 1) {
        if (tid < off) {
            sx[tid] += sx[tid + off]; sy[tid] += sy[tid + off];
            mx[tid] = fmaxf(mx[tid], mx[tid + off]);
            my[tid] = fmaxf(my[tid], my[tid + off]);
        }
        __syncthreads();
    }
    if (tid == 0) {
        g_poolS[2 * c]     = sx[0]; g_poolS[2 * c + 1] = sy[0];
        g_poolM[2 * c]     = mx[0]; g_poolM[2 * c + 1] = my[0];
    }
}

__global__ void head_kernel(const float* __restrict__ fw1,
                            const float* __restrict__ fb1,
                            const float* __restrict__ fw2,
                            const float* __restrict__ fb2,
                            float* __restrict__ out) {
    __shared__ float pooled[128];
    __shared__ float red[64];
    int tid = threadIdx.x;
    pooled[tid]      = g_poolS[tid] * (1.0f / NN);
    pooled[tid + 64] = g_poolM[tid];
    __syncthreads();

    float acc = fb1[tid];
#pragma unroll 4
    for (int k = 0; k < 128; k++) acc = fmaf(pooled[k], fw1[k * 64 + tid], acc);
    red[tid] = fmaxf(acc, 0.f) * fw2[tid];
    __syncthreads();
    if (tid == 0) {
        float t = 0.f;
        for (int i = 0; i < 64; i++) t += red[i];
        out[0] = t + fb2[0];
    }
}

// ---------------- launcher ---------------------------------------------------
extern "C" void kernel_launch(void* const* d_in, const int* in_sizes, int n_in,
                              void* d_out, int out_size) {
    const float* x   = (const float*)d_in[0];
    const int*   ei  = (const int*)d_in[1];
    const float* W1  = (const float*)d_in[2];
    const float* b1  = (const float*)d_in[3];
    const float* W2  = (const float*)d_in[4];
    const float* b2  = (const float*)d_in[5];
    const float* W3  = (const float*)d_in[6];
    const float* b3  = (const float*)d_in[7];
    const float* fw1 = (const float*)d_in[8];
    const float* fb1 = (const float*)d_in[9];
    const float* fw2 = (const float*)d_in[10];
    const float* fb2 = (const float*)d_in[11];
    float* out = (float*)d_out;

    float* hA;
    cudaGetSymbolAddress((void**)&hA, g_hA);

    static cudaStream_t sB = nullptr;
    static cudaEvent_t  eF = nullptr, eJ = nullptr;
    if (sB == nullptr) {
        cudaStreamCreateWithFlags(&sB, cudaStreamNonBlocking);
        cudaEventCreateWithFlags(&eF, cudaEventDisableTiming);
        cudaEventCreateWithFlags(&eJ, cudaEventDisableTiming);
    }

    const int NB_I  = (CAP / 4 + 255) / 256;   // 977
    const int NB_N  = (NN + 255) / 256;        // 196
    const int NB_E4 = (EE / 4 + 255) / 256;    // 782
    const int GB    = (NN + 255) / 256;        // 196 blocks x 256 rows

    init_kernel<<<NB_I, 256>>>();
    count_kernel<<<NB_E4, 256>>>(ei);
    alloc_kernel<<<NB_N, 256>>>();

    cudaEventRecord(eF, 0);
    cudaStreamWaitEvent(sB, eF, 0);
    gemm_tile_kernel<DIN><<<GB, 128, 0, sB>>>(x, W1, NN);
    cudaEventRecord(eJ, sB);

    scatter_kernel<<<NB_E4, 256>>>(ei);

    cudaStreamWaitEvent(0, eJ, 0);

    agg_kernel<<<AB, 256>>>(b1);
    gemm_tile_kernel<HH><<<GB, 128>>>(hA, W2, NN);
    agg_kernel<<<AB, 256>>>(b2);
    gemm_tile_kernel<HH><<<GB, 128>>>(hA, W3, NN);
    agg_pool_kernel<<<AB, 256>>>(b3);

    pool_reduce_kernel<<<32, 256>>>();
    head_kernel<<<1, 64>>>(fw1, fb1, fw2, fb2, out);
}

// round 7
// speedup vs baseline: 1.0742x; 1.0742x over previous
#include <cuda_runtime.h>
#include <cuda_fp16.h>

#define NN   50000
#define EE   800000
#define DIN  128
#define HH   64
#define AB   6250                 // agg blocks: 8 rows x 6250 = 50000 exactly
#define CAP  (EE + 4 * NN)        // padded CSR capacity (1,000,000; mult of 4)

// ---------------- scratch (static device globals: no allocation) -------------
__device__ int    g_deg[NN];
__device__ int2   g_row[NN];                 // (rowstart, real deg)
__device__ int    g_tot;
__device__ float  g_dinv[NN];
__device__ int    g_rank[EE];                // edge rank within dst segment
__device__ int    g_col[CAP];                // src per CSR slot; pads = NN (dummy)
__device__ __align__(16) __half g_hH[(size_t)(NN + 1) * HH]; // h' = dinv*h (fp16); row NN = 0
__device__ __align__(16) float  g_hA[(size_t)NN * HH];       // agg out, fp32
__device__ float2 g_psT[32 * AB];            // pool sum partials [lanecol][blk]
__device__ float2 g_pmT[32 * AB];            // pool max partials
__device__ float  g_poolS[HH];
__device__ float  g_poolM[HH];

typedef unsigned long long u64;

__device__ __forceinline__ void ffma2(u64& d, u64 a, u64 b) {
    asm("fma.rn.f32x2 %0, %1, %2, %0;" : "+l"(d) : "l"(a), "l"(b));
}
__device__ __forceinline__ u64 pack2(float lo, float hi) {
    u64 r; asm("mov.b64 %0, {%1, %2};" : "=l"(r) : "f"(lo), "f"(hi)); return r;
}
__device__ __forceinline__ void unpack2(float& lo, float& hi, u64 v) {
    asm("mov.b64 {%0, %1}, %2;" : "=f"(lo), "=f"(hi) : "l"(v));
}

// ---------------- setup kernels ----------------------------------------------
// zero deg/tot/dummy-row; fill g_col with NN so pad slots gather zeros
__global__ void init_kernel() {
    int i = blockIdx.x * blockDim.x + threadIdx.x;
    if (i < NN) g_deg[i] = 0;
    if (i == 0) g_tot = 0;
    if (i < 8) reinterpret_cast<int4*>(g_hH + (size_t)NN * HH)[i] = make_int4(0, 0, 0, 0);
    if (i < CAP / 4) reinterpret_cast<int4*>(g_col)[i] = make_int4(NN, NN, NN, NN);
}

// histogram; atomic return value doubles as the edge's rank within its segment
__global__ void count_kernel(const int* __restrict__ ei) {
    int i = blockIdx.x * blockDim.x + threadIdx.x;
    if (i >= EE / 4) return;
    int4 d4 = reinterpret_cast<const int4*>(ei + EE)[i];
    int4 r4;
    r4.x = atomicAdd(&g_deg[d4.x], 1);
    r4.y = atomicAdd(&g_deg[d4.y], 1);
    r4.z = atomicAdd(&g_deg[d4.z], 1);
    r4.w = atomicAdd(&g_deg[d4.w], 1);
    reinterpret_cast<int4*>(g_rank)[i] = r4;
}

// warp-aggregated segment allocator (pads each segment to a multiple of 4) + dinv
__global__ void alloc_kernel() {
    int i    = blockIdx.x * blockDim.x + threadIdx.x;
    int lane = threadIdx.x & 31;
    int d    = (i < NN) ? g_deg[i] : 0;
    int pd   = (d + 3) & ~3;

    int x = pd;
#pragma unroll
    for (int off = 1; off < 32; off <<= 1) {
        int v = __shfl_up_sync(0xFFFFFFFFu, x, off);
        if (lane >= off) x += v;
    }
    int wsum = __shfl_sync(0xFFFFFFFFu, x, 31);
    int base = 0;
    if (lane == 31) base = atomicAdd(&g_tot, wsum);
    base = __shfl_sync(0xFFFFFFFFu, base, 31);

    if (i < NN) {
        g_row[i]  = make_int2(base + x - pd, d);
        g_dinv[i] = rsqrtf((float)d + 1.0f);
    }
}

// atomic-free scatter: slot = rowstart[dst] + rank[e]
__global__ void scatter_kernel(const int* __restrict__ ei) {
    int i = blockIdx.x * blockDim.x + threadIdx.x;
    if (i >= EE / 4) return;
    int4 s4 = reinterpret_cast<const int4*>(ei)[i];
    int4 d4 = reinterpret_cast<const int4*>(ei + EE)[i];
    int4 r4 = reinterpret_cast<const int4*>(g_rank)[i];
    g_col[g_row[d4.x].x + r4.x] = s4.x;
    g_col[g_row[d4.y].x + r4.y] = s4.y;
    g_col[g_row[d4.z].x + r4.z] = s4.z;
    g_col[g_row[d4.w].x + r4.w] = s4.w;
}

// ---------------- GEMM: hH[N,64] = fp16( dinv[i] * (X[N,K] @ W[K,64]) ) ------
// 2 rows x 32 cols per thread (acc = 32 u64 = 64 regs). Column half c2 is
// WARP-UNIFORM (tid>>6) so W smem reads are conflict-free broadcasts.
// Per thread per k: 8 LDS.128 + 32 ffma2. Block covers 128 rows; grid = 391.
template <int K>
__global__ __launch_bounds__(128) void gemm_kernel(const float* __restrict__ X,
                                                   const float* __restrict__ W,
                                                   int nrows) {
    __shared__ float Wsm[K * 64];
    for (int i = threadIdx.x; i < K * 16; i += 128)
        reinterpret_cast<float4*>(Wsm)[i] = reinterpret_cast<const float4*>(W)[i];
    __syncthreads();

    const int c2 = threadIdx.x >> 6;          // warp-uniform column half (0/1)
    const int rq = threadIdx.x & 63;
    const int r0 = blockIdx.x * 128 + rq * 2; // 2 consecutive rows per thread
    if (r0 >= nrows) return;
    const bool rv1 = (r0 + 1 < nrows);

    u64 acc0[16], acc1[16];
#pragma unroll
    for (int c = 0; c < 16; c++) { acc0[c] = 0ull; acc1[c] = 0ull; }

    const float4* xp = reinterpret_cast<const float4*>(X);

#pragma unroll 1
    for (int kc = 0; kc < K / 4; kc++) {
        float4 xa = xp[(size_t)r0 * (K / 4) + kc];
        float4 xb = rv1 ? xp[(size_t)(r0 + 1) * (K / 4) + kc]
                        : make_float4(0.f, 0.f, 0.f, 0.f);
        const float xa4[4] = {xa.x, xa.y, xa.z, xa.w};
        const float xb4[4] = {xb.x, xb.y, xb.z, xb.w};
#pragma unroll
        for (int q = 0; q < 4; q++) {
            const ulonglong2* wr = reinterpret_cast<const ulonglong2*>(
                Wsm + (kc * 4 + q) * 64 + c2 * 32);
            ulonglong2 t0 = wr[0], t1 = wr[1], t2 = wr[2], t3 = wr[3];
            ulonglong2 t4 = wr[4], t5 = wr[5], t6 = wr[6], t7 = wr[7];
            const u64 wv[16] = {t0.x, t0.y, t1.x, t1.y, t2.x, t2.y, t3.x, t3.y,
                                t4.x, t4.y, t5.x, t5.y, t6.x, t6.y, t7.x, t7.y};
            const u64 sa = pack2(xa4[q], xa4[q]);
            const u64 sb = pack2(xb4[q], xb4[q]);
#pragma unroll
            for (int c = 0; c < 16; c++) {
                ffma2(acc0[c], sa, wv[c]);
                ffma2(acc1[c], sb, wv[c]);
            }
        }
    }

    // epilogue: scale by dinv, cvt fp16, store this thread's 32 cols per row
    {
        float di = g_dinv[r0];
        u64 dd = pack2(di, di);
        uint4* yp = reinterpret_cast<uint4*>((char*)g_hH + (size_t)r0 * 128 + c2 * 64);
#pragma unroll
        for (int g = 0; g < 4; g++) {
            unsigned rr[4];
#pragma unroll
            for (int j = 0; j < 4; j++) {
                float lo, hi;
                unpack2(lo, hi, acc0[4 * g + j]);
                __half2 h2 = __floats2half2_rn(lo * di, hi * di);
                rr[j] = *reinterpret_cast<unsigned*>(&h2);
            }
            uint4 o; o.x = rr[0]; o.y = rr[1]; o.z = rr[2]; o.w = rr[3];
            yp[g] = o;
        }
        (void)dd;
    }
    if (rv1) {
        float di = g_dinv[r0 + 1];
        uint4* yp = reinterpret_cast<uint4*>((char*)g_hH + (size_t)(r0 + 1) * 128 + c2 * 64);
#pragma unroll
        for (int g = 0; g < 4; g++) {
            unsigned rr[4];
#pragma unroll
            for (int j = 0; j < 4; j++) {
                float lo, hi;
                unpack2(lo, hi, acc1[4 * g + j]);
                __half2 h2 = __floats2half2_rn(lo * di, hi * di);
                rr[j] = *reinterpret_cast<unsigned*>(&h2);
            }
            uint4 o; o.x = rr[0]; o.y = rr[1]; o.z = rr[2]; o.w = rr[3];
            yp[g] = o;
        }
    }
}

// ---------------- aggregation: warp per node, shfl-free fp16 gather ----------
// A[i] = relu( dinv_i * (sum_j h'_j + h'_i) + b ),   h' = dinv*h (fp16)
__device__ __forceinline__ float2 agg_row(int row, int lane) {
    int2 rd     = g_row[row];
    int  padded = (rd.y + 3) & ~3;            // pad slots index dummy zero row
    const int*      cp = g_col + rd.x;
    const unsigned* hb = reinterpret_cast<const unsigned*>(g_hH);

    float ax = 0.f, ay = 0.f;
#pragma unroll 4
    for (int p = 0; p < padded; p++) {
        int sj = __ldg(cp + p);               // warp-uniform broadcast load
        unsigned hv = __ldg(hb + sj * 32 + lane);
        float2 f = __half22float2(*reinterpret_cast<__half2*>(&hv));
        ax += f.x;
        ay += f.y;
    }
    return make_float2(ax, ay);
}

__device__ __forceinline__ float2 agg_finish(int row, int lane, float2 a,
                                             const float* bias) {
    const unsigned* hb = reinterpret_cast<const unsigned*>(g_hH);
    unsigned hs = hb[row * 32 + lane];
    float2 fs = __half22float2(*reinterpret_cast<__half2*>(&hs));
    float di = g_dinv[row];
    float2 b = reinterpret_cast<const float2*>(bias)[lane];
    float ox = fmaf(di, a.x + fs.x, b.x);
    float oy = fmaf(di, a.y + fs.y, b.y);
    return make_float2(fmaxf(ox, 0.f), fmaxf(oy, 0.f));
}

__global__ void agg_kernel(const float* __restrict__ bias) {
    int warp = threadIdx.x >> 5;
    int lane = threadIdx.x & 31;
    int row  = blockIdx.x * 8 + warp;
    float2 a = agg_row(row, lane);
    float2 o = agg_finish(row, lane, a, bias);
    reinterpret_cast<float2*>(g_hA)[row * 32 + lane] = o;
}

// layer-3 agg with fused pooling partials (activations never materialized)
__global__ void agg_pool_kernel(const float* __restrict__ bias) {
    __shared__ float2 s_sum[8][32];
    __shared__ float2 s_max[8][32];
    int warp = threadIdx.x >> 5;
    int lane = threadIdx.x & 31;
    int row  = blockIdx.x * 8 + warp;

    float2 a = agg_row(row, lane);
    float2 o = agg_finish(row, lane, a, bias);
    s_sum[warp][lane] = o;
    s_max[warp][lane] = o;
    __syncthreads();

    if (threadIdx.x < 32) {
        float2 S = make_float2(0.f, 0.f), M = make_float2(0.f, 0.f);
#pragma unroll
        for (int w = 0; w < 8; w++) {
            float2 v = s_sum[w][threadIdx.x];
            S.x += v.x; S.y += v.y;
            float2 m = s_max[w][threadIdx.x];
            M.x = fmaxf(M.x, m.x); M.y = fmaxf(M.y, m.y);
        }
        g_psT[threadIdx.x * AB + blockIdx.x] = S;   // transposed: coalesced reduce
        g_pmT[threadIdx.x * AB + blockIdx.x] = M;
    }
}

// collapse 6250 partials per lane-column pair (32 blocks, coalesced reads)
__global__ void pool_reduce_kernel() {
    __shared__ float sx[256], sy[256], mx[256], my[256];
    int c   = blockIdx.x;
    int tid = threadIdx.x;
    float ax = 0.f, ay = 0.f, bx = 0.f, by = 0.f;
    for (int i = tid; i < AB; i += 256) {
        float2 s = g_psT[c * AB + i];
        ax += s.x; ay += s.y;
        float2 m = g_pmT[c * AB + i];
        bx = fmaxf(bx, m.x); by = fmaxf(by, m.y);
    }
    sx[tid] = ax; sy[tid] = ay; mx[tid] = bx; my[tid] = by;
    __syncthreads();
    for (int off = 128; off > 0; off >>= 1) {
        if (tid < off) {
            sx[tid] += sx[tid + off]; sy[tid] += sy[tid + off];
            mx[tid] = fmaxf(mx[tid], mx[tid + off]);
            my[tid] = fmaxf(my[tid], my[tid + off]);
        }
        __syncthreads();
    }
    if (tid == 0) {
        g_poolS[2 * c]     = sx[0]; g_poolS[2 * c + 1] = sy[0];
        g_poolM[2 * c]     = mx[0]; g_poolM[2 * c + 1] = my[0];
    }
}

__global__ void head_kernel(const float* __restrict__ fw1,
                            const float* __restrict__ fb1,
                            const float* __restrict__ fw2,
                            const float* __restrict__ fb2,
                            float* __restrict__ out) {
    __shared__ float pooled[128];
    __shared__ float red[64];
    int tid = threadIdx.x;                    // 64 threads
    pooled[tid]      = g_poolS[tid] * (1.0f / NN);
    pooled[tid + 64] = g_poolM[tid];
    __syncthreads();

    float acc = fb1[tid];
#pragma unroll 4
    for (int k = 0; k < 128; k++) acc = fmaf(pooled[k], fw1[k * 64 + tid], acc);
    red[tid] = fmaxf(acc, 0.f) * fw2[tid];
    __syncthreads();
    if (tid == 0) {
        float t = 0.f;
        for (int i = 0; i < 64; i++) t += red[i];
        out[0] = t + fb2[0];
    }
}

// ---------------- launcher ---------------------------------------------------
extern "C" void kernel_launch(void* const* d_in, const int* in_sizes, int n_in,
                              void* d_out, int out_size) {
    const float* x   = (const float*)d_in[0];
    const int*   ei  = (const int*)d_in[1];
    const float* W1  = (const float*)d_in[2];
    const float* b1  = (const float*)d_in[3];
    const float* W2  = (const float*)d_in[4];
    const float* b2  = (const float*)d_in[5];
    const float* W3  = (const float*)d_in[6];
    const float* b3  = (const float*)d_in[7];
    const float* fw1 = (const float*)d_in[8];
    const float* fb1 = (const float*)d_in[9];
    const float* fw2 = (const float*)d_in[10];
    const float* fb2 = (const float*)d_in[11];
    float* out = (float*)d_out;

    float* hA;
    cudaGetSymbolAddress((void**)&hA, g_hA);

    // side stream + events (host-side only; created once, reused)
    static cudaStream_t sB = nullptr;
    static cudaEvent_t  eF = nullptr, eJ = nullptr;
    if (sB == nullptr) {
        cudaStreamCreateWithFlags(&sB, cudaStreamNonBlocking);
        cudaEventCreateWithFlags(&eF, cudaEventDisableTiming);
        cudaEventCreateWithFlags(&eJ, cudaEventDisableTiming);
    }

    const int NB_I  = (CAP / 4 + 255) / 256;   // 977
    const int NB_N  = (NN + 255) / 256;        // 196
    const int NB_E4 = (EE / 4 + 255) / 256;    // 782
    const int GB    = (NN + 127) / 128;        // 391 blocks x 128 rows

    // CSR build (through alloc) on the main stream
    init_kernel<<<NB_I, 256>>>();
    count_kernel<<<NB_E4, 256>>>(ei);
    alloc_kernel<<<NB_N, 256>>>();

    // fork: GEMM1 (needs dinv from alloc) runs on sB concurrently with scatter
    cudaEventRecord(eF, 0);
    cudaStreamWaitEvent(sB, eF, 0);
    gemm_kernel<DIN><<<GB, 128, 0, sB>>>(x, W1, NN);
    cudaEventRecord(eJ, sB);

    scatter_kernel<<<NB_E4, 256>>>(ei);

    // join: agg1 needs both CSR and GEMM1
    cudaStreamWaitEvent(0, eJ, 0);

    agg_kernel<<<AB, 256>>>(b1);
    gemm_kernel<HH><<<GB, 128>>>(hA, W2, NN);
    agg_kernel<<<AB, 256>>>(b2);
    gemm_kernel<HH><<<GB, 128>>>(hA, W3, NN);
    agg_pool_kernel<<<AB, 256>>>(b3);

    pool_reduce_kernel<<<32, 256>>>();
    head_kernel<<<1, 64>>>(fw1, fb1, fw2, fb2, out);
}

// round 9
// speedup vs baseline: 1.4404x; 1.3409x over previous
#include <cuda_runtime.h>
#include <cuda_fp16.h>
#include <cstdint>

#define NN   50000
#define EE   800000
#define DIN  128
#define HH   64
#define AB   6250                 // agg blocks: 8 rows x 6250 = 50000 exactly
#define CAP  (EE + 4 * NN)        // padded CSR capacity (1,000,000; mult of 4)
#define GTB  391                  // gemm tile blocks: 391 x 128 rows >= NN

// ---------------- scratch (static device globals: no allocation) -------------
__device__ int    g_deg[NN];
__device__ int2   g_row[NN];                 // (rowstart, real deg)
__device__ int    g_tot;
__device__ float  g_dinv[NN];
__device__ int    g_rank[EE];                // edge rank within dst segment
__device__ int    g_col[CAP];                // src per CSR slot; pads = NN (dummy)
__device__ __align__(16) __half g_xh[(size_t)NN * DIN];      // fp16 x
__device__ __align__(16) __half g_w1t[HH * DIN];             // W1^T [64][128] fp16
__device__ __align__(16) __half g_w2t[HH * HH];              // W2^T [64][64]
__device__ __align__(16) __half g_w3t[HH * HH];              // W3^T [64][64]
__device__ __align__(16) __half g_hH[(size_t)(NN + 1) * HH]; // gemm out: dinv*h fp16; row NN = 0
__device__ __align__(16) __half g_hAH[(size_t)NN * HH];      // agg out fp16 (gemm2/3 input)
__device__ float2 g_psT[32 * AB];            // pool sum partials [lanecol][blk]
__device__ float2 g_pmT[32 * AB];            // pool max partials
__device__ float  g_poolS[HH];
__device__ float  g_poolM[HH];

// ---------------- PTX helpers -------------------------------------------------
__device__ __forceinline__ uint32_t smem_u32(const void* p) {
    uint32_t a;
    asm("{ .reg .u64 t; cvta.to.shared.u64 t, %1; cvt.u32.u64 %0, t; }"
        : "=r"(a) : "l"(p));
    return a;
}
__device__ __forceinline__ void ldsm4(uint32_t* r, uint32_t addr) {
    asm volatile("ldmatrix.sync.aligned.m8n8.x4.shared.b16 {%0,%1,%2,%3}, [%4];"
                 : "=r"(r[0]), "=r"(r[1]), "=r"(r[2]), "=r"(r[3]) : "r"(addr));
}
__device__ __forceinline__ void mma16816(float* c, const uint32_t* a,
                                         uint32_t b0, uint32_t b1) {
    asm volatile(
        "mma.sync.aligned.m16n8k16.row.col.f32.f16.f16.f32 "
        "{%0,%1,%2,%3}, {%4,%5,%6,%7}, {%8,%9}, {%0,%1,%2,%3};"
        : "+f"(c[0]), "+f"(c[1]), "+f"(c[2]), "+f"(c[3])
        : "r"(a[0]), "r"(a[1]), "r"(a[2]), "r"(a[3]), "r"(b0), "r"(b1));
}

// ---------------- setup kernels ----------------------------------------------
__global__ void init_kernel() {
    int i = blockIdx.x * blockDim.x + threadIdx.x;
    if (i < NN) g_deg[i] = 0;
    if (i == 0) g_tot = 0;
    if (i < 8) reinterpret_cast<int4*>(g_hH + (size_t)NN * HH)[i] = make_int4(0, 0, 0, 0);
    if (i < CAP / 4) reinterpret_cast<int4*>(g_col)[i] = make_int4(NN, NN, NN, NN);
}

__global__ void count_kernel(const int* __restrict__ ei) {
    int i = blockIdx.x * blockDim.x + threadIdx.x;
    if (i >= EE / 4) return;
    int4 d4 = reinterpret_cast<const int4*>(ei + EE)[i];
    int4 r4;
    r4.x = atomicAdd(&g_deg[d4.x], 1);
    r4.y = atomicAdd(&g_deg[d4.y], 1);
    r4.z = atomicAdd(&g_deg[d4.z], 1);
    r4.w = atomicAdd(&g_deg[d4.w], 1);
    reinterpret_cast<int4*>(g_rank)[i] = r4;
}

__global__ void alloc_kernel() {
    int i    = blockIdx.x * blockDim.x + threadIdx.x;
    int lane = threadIdx.x & 31;
    int d    = (i < NN) ? g_deg[i] : 0;
    int pd   = (d + 3) & ~3;

    int x = pd;
#pragma unroll
    for (int off = 1; off < 32; off <<= 1) {
        int v = __shfl_up_sync(0xFFFFFFFFu, x, off);
        if (lane >= off) x += v;
    }
    int wsum = __shfl_sync(0xFFFFFFFFu, x, 31);
    int base = 0;
    if (lane == 31) base = atomicAdd(&g_tot, wsum);
    base = __shfl_sync(0xFFFFFFFFu, base, 31);

    if (i < NN) {
        g_row[i]  = make_int2(base + x - pd, d);
        g_dinv[i] = rsqrtf((float)d + 1.0f);
    }
}

__global__ void scatter_kernel(const int* __restrict__ ei) {
    int i = blockIdx.x * blockDim.x + threadIdx.x;
    if (i >= EE / 4) return;
    int4 s4 = reinterpret_cast<const int4*>(ei)[i];
    int4 d4 = reinterpret_cast<const int4*>(ei + EE)[i];
    int4 r4 = reinterpret_cast<const int4*>(g_rank)[i];
    g_col[g_row[d4.x].x + r4.x] = s4.x;
    g_col[g_row[d4.y].x + r4.y] = s4.y;
    g_col[g_row[d4.z].x + r4.z] = s4.z;
    g_col[g_row[d4.w].x + r4.w] = s4.w;
}

// ---------------- fp16 conversion kernels ------------------------------------
__global__ void xconv_kernel(const float* __restrict__ x) {
    int i = blockIdx.x * blockDim.x + threadIdx.x;   // over float4s: NN*DIN/4
    if (i >= NN * DIN / 4) return;
    float4 v = reinterpret_cast<const float4*>(x)[i];
    __half2 a = __floats2half2_rn(v.x, v.y);
    __half2 b = __floats2half2_rn(v.z, v.w);
    uint2 o = make_uint2(*reinterpret_cast<unsigned*>(&a), *reinterpret_cast<unsigned*>(&b));
    reinterpret_cast<uint2*>(g_xh)[i] = o;
}

__global__ void wconv_kernel(const float* __restrict__ W1,
                             const float* __restrict__ W2,
                             const float* __restrict__ W3) {
    int i = blockIdx.x * blockDim.x + threadIdx.x;
    if (i < DIN * HH) {
        int k = i / HH, n = i % HH;
        g_w1t[n * DIN + k] = __float2half(W1[i]);
    } else if (i < DIN * HH + HH * HH) {
        int j = i - DIN * HH, k = j / HH, n = j % HH;
        g_w2t[n * HH + k] = __float2half(W2[j]);
    } else if (i < DIN * HH + 2 * HH * HH) {
        int j = i - DIN * HH - HH * HH, k = j / HH, n = j % HH;
        g_w3t[n * HH + k] = __float2half(W3[j]);
    }
}

// ---------------- HMMA GEMM: hH = fp16( dinv * (A[N,K] @ Bt[64,K]^T) ) -------
// Per CTA: 128 rows x 64 cols, 4 warps (warp w = rows 32w..32w+31).
// Smem padded row stride S = K+8 halves => ldmatrix conflict-free (4-bank
// rotation per row). mma.sync m16n8k16, fp32 accum.
template <int K>
__global__ __launch_bounds__(128) void gemm_mma_kernel(const __half* __restrict__ Asrc,
                                                       const __half* __restrict__ Bt,
                                                       int nrows) {
    constexpr int S  = K + 8;                 // halves per smem row
    constexpr int RQ = K / 8;                 // uint4 chunks per source row
    extern __shared__ __align__(16) __half smem[];
    __half* As = smem;                        // 128 x S
    __half* Bs = smem + 128 * S;              // 64 x S
    const int tid = threadIdx.x, wid = tid >> 5, lane = tid & 31;
    const int rowbase = blockIdx.x * 128;

    // fill A (guard rows past nrows with zeros)
    for (int idx = tid; idx < 128 * RQ; idx += 128) {
        int r = idx / RQ, j = idx % RQ;
        uint4 v = make_uint4(0, 0, 0, 0);
        if (rowbase + r < nrows)
            v = reinterpret_cast<const uint4*>(Asrc)[(size_t)(rowbase + r) * RQ + j];
        *reinterpret_cast<uint4*>(As + r * S + j * 8) = v;
    }
    // fill B (W^T: 64 rows x K)
    for (int idx = tid; idx < 64 * RQ; idx += 128) {
        int r = idx / RQ, j = idx % RQ;
        uint4 v = reinterpret_cast<const uint4*>(Bt)[(size_t)r * RQ + j];
        *reinterpret_cast<uint4*>(Bs + r * S + j * 8) = v;
    }
    __syncthreads();

    float acc[2][8][4];
#pragma unroll
    for (int rg = 0; rg < 2; rg++)
#pragma unroll
        for (int ng = 0; ng < 8; ng++)
#pragma unroll
            for (int q = 0; q < 4; q++) acc[rg][ng][q] = 0.f;

    const uint32_t sA = smem_u32(As), sB = smem_u32(Bs);

#pragma unroll
    for (int ks = 0; ks < K / 16; ks++) {
        // A fragments: 2 row-groups of m16k16
        uint32_t a[2][4];
#pragma unroll
        for (int rg = 0; rg < 2; rg++) {
            int row = wid * 32 + rg * 16 + (lane & 15);
            uint32_t addr = sA + (uint32_t)(row * S + ks * 16 + (lane >> 4) * 8) * 2;
            ldsm4(a[rg], addr);
        }
        // B fragments: 4 x4 loads cover 8 n-groups
        uint32_t b[4][4];
#pragma unroll
        for (int np = 0; np < 4; np++) {
            int row = np * 16 + (lane & 7) + ((lane >> 4) << 3);
            int col = ks * 16 + (((lane >> 3) & 1) << 3);
            uint32_t addr = sB + (uint32_t)(row * S + col) * 2;
            ldsm4(b[np], addr);
        }
#pragma unroll
        for (int rg = 0; rg < 2; rg++)
#pragma unroll
            for (int ng = 0; ng < 8; ng++)
                mma16816(acc[rg][ng], a[rg],
                         b[ng >> 1][(ng & 1) * 2], b[ng >> 1][(ng & 1) * 2 + 1]);
    }

    // epilogue: D[m16n8] thread map: c0,c1 -> row lane/4, cols 2*(lane%4)+{0,1};
    // c2,c3 -> row lane/4+8. Scale by dinv[row], store half2.
#pragma unroll
    for (int rg = 0; rg < 2; rg++) {
        int ra = rowbase + wid * 32 + rg * 16 + (lane >> 2);
        int rb = ra + 8;
        float da = (ra < nrows) ? g_dinv[ra] : 0.f;
        float db = (rb < nrows) ? g_dinv[rb] : 0.f;
#pragma unroll
        for (int ng = 0; ng < 8; ng++) {
            int col = ng * 8 + (lane & 3) * 2;
            if (ra < nrows) {
                __half2 h = __floats2half2_rn(acc[rg][ng][0] * da, acc[rg][ng][1] * da);
                *reinterpret_cast<__half2*>(g_hH + (size_t)ra * HH + col) = h;
            }
            if (rb < nrows) {
                __half2 h = __floats2half2_rn(acc[rg][ng][2] * db, acc[rg][ng][3] * db);
                *reinterpret_cast<__half2*>(g_hH + (size_t)rb * HH + col) = h;
            }
        }
    }
}

// ---------------- aggregation: warp per node, shfl-free fp16 gather ----------
// A[i] = relu( dinv_i * (sum_j h'_j + h'_i) + b ),   h' = dinv*h (fp16)
__device__ __forceinline__ float2 agg_row(int row, int lane) {
    int2 rd     = g_row[row];
    int  padded = (rd.y + 3) & ~3;            // pad slots index dummy zero row
    const int*      cp = g_col + rd.x;
    const unsigned* hb = reinterpret_cast<const unsigned*>(g_hH);

    float ax = 0.f, ay = 0.f;
#pragma unroll 4
    for (int p = 0; p < padded; p++) {
        int sj = __ldg(cp + p);               // warp-uniform broadcast load
        unsigned hv = __ldg(hb + sj * 32 + lane);
        float2 f = __half22float2(*reinterpret_cast<const __half2*>(&hv));
        ax += f.x;
        ay += f.y;
    }
    return make_float2(ax, ay);
}

__device__ __forceinline__ float2 agg_finish(int row, int lane, float2 a,
                                             const float* bias) {
    const unsigned* hb = reinterpret_cast<const unsigned*>(g_hH);
    unsigned hs = hb[row * 32 + lane];
    float2 fs = __half22float2(*reinterpret_cast<const __half2*>(&hs));
    float di = g_dinv[row];
    float2 b = reinterpret_cast<const float2*>(bias)[lane];
    float ox = fmaf(di, a.x + fs.x, b.x);
    float oy = fmaf(di, a.y + fs.y, b.y);
    return make_float2(fmaxf(ox, 0.f), fmaxf(oy, 0.f));
}

__global__ void agg_kernel(const float* __restrict__ bias) {
    int warp = threadIdx.x >> 5;
    int lane = threadIdx.x & 31;
    int row  = blockIdx.x * 8 + warp;
    float2 a = agg_row(row, lane);
    float2 o = agg_finish(row, lane, a, bias);
    __half2 oh = __floats2half2_rn(o.x, o.y);
    reinterpret_cast<unsigned*>(g_hAH)[row * 32 + lane] =
        *reinterpret_cast<unsigned*>(&oh);
}

// layer-3 agg with fused pooling partials (activations never materialized)
__global__ void agg_pool_kernel(const float* __restrict__ bias) {
    __shared__ float2 s_sum[8][32];
    int warp = threadIdx.x >> 5;
    int lane = threadIdx.x & 31;
    int row  = blockIdx.x * 8 + warp;

    float2 a = agg_row(row, lane);
    float2 o = agg_finish(row, lane, a, bias);
    s_sum[warp][lane] = o;
    __syncthreads();

    if (threadIdx.x < 64) {
        int w0 = threadIdx.x >> 5;            // 0/1: sums vs maxes split
        int c  = threadIdx.x & 31;
        if (w0 == 0) {
            float2 S = make_float2(0.f, 0.f);
#pragma unroll
            for (int w = 0; w < 8; w++) {
                float2 v = s_sum[w][c];
                S.x += v.x; S.y += v.y;
            }
            g_psT[c * AB + blockIdx.x] = S;
        } else {
            float2 M = make_float2(0.f, 0.f);
#pragma unroll
            for (int w = 0; w < 8; w++) {
                float2 v = s_sum[w][c];
                M.x = fmaxf(M.x, v.x); M.y = fmaxf(M.y, v.y);
            }
            g_pmT[c * AB + blockIdx.x] = M;
        }
    }
}

__global__ void pool_reduce_kernel() {
    __shared__ float sx[256], sy[256], mx[256], my[256];
    int c   = blockIdx.x;
    int tid = threadIdx.x;
    float ax = 0.f, ay = 0.f, bx = 0.f, by = 0.f;
    for (int i = tid; i < AB; i += 256) {
        float2 s = g_psT[c * AB + i];
        ax += s.x; ay += s.y;
        float2 m = g_pmT[c * AB + i];
        bx = fmaxf(bx, m.x); by = fmaxf(by, m.y);
    }
    sx[tid] = ax; sy[tid] = ay; mx[tid] = bx; my[tid] = by;
    __syncthreads();
    for (int off = 128; off > 0; off >>= 1) {
        if (tid < off) {
            sx[tid] += sx[tid + off]; sy[tid] += sy[tid + off];
            mx[tid] = fmaxf(mx[tid], mx[tid + off]);
            my[tid] = fmaxf(my[tid], my[tid + off]);
        }
        __syncthreads();
    }
    if (tid == 0) {
        g_poolS[2 * c]     = sx[0]; g_poolS[2 * c + 1] = sy[0];
        g_poolM[2 * c]     = mx[0]; g_poolM[2 * c + 1] = my[0];
    }
}

__global__ void head_kernel(const float* __restrict__ fw1,
                            const float* __restrict__ fb1,
                            const float* __restrict__ fw2,
                            const float* __restrict__ fb2,
                            float* __restrict__ out) {
    __shared__ float pooled[128];
    __shared__ float red[64];
    int tid = threadIdx.x;                    // 64 threads
    pooled[tid]      = g_poolS[tid] * (1.0f / NN);
    pooled[tid + 64] = g_poolM[tid];
    __syncthreads();

    float acc = fb1[tid];
#pragma unroll 4
    for (int k = 0; k < 128; k++) acc = fmaf(pooled[k], fw1[k * 64 + tid], acc);
    red[tid] = fmaxf(acc, 0.f) * fw2[tid];
    __syncthreads();
    if (tid == 0) {
        float t = 0.f;
        for (int i = 0; i < 64; i++) t += red[i];
        out[0] = t + fb2[0];
    }
}

// ---------------- launcher ---------------------------------------------------
extern "C" void kernel_launch(void* const* d_in, const int* in_sizes, int n_in,
                              void* d_out, int out_size) {
    const float* x   = (const float*)d_in[0];
    const int*   ei  = (const int*)d_in[1];
    const float* W1  = (const float*)d_in[2];
    const float* b1  = (const float*)d_in[3];
    const float* W2  = (const float*)d_in[4];
    const float* b2  = (const float*)d_in[5];
    const float* W3  = (const float*)d_in[6];
    const float* b3  = (const float*)d_in[7];
    const float* fw1 = (const float*)d_in[8];
    const float* fb1 = (const float*)d_in[9];
    const float* fw2 = (const float*)d_in[10];
    const float* fb2 = (const float*)d_in[11];
    float* out = (float*)d_out;

    __half *xh, *w1t, *w2t, *w3t, *hAH;
    cudaGetSymbolAddress((void**)&xh,  g_xh);
    cudaGetSymbolAddress((void**)&w1t, g_w1t);
    cudaGetSymbolAddress((void**)&w2t, g_w2t);
    cudaGetSymbolAddress((void**)&w3t, g_w3t);
    cudaGetSymbolAddress((void**)&hAH, g_hAH);

    // host-side stream/event/attr setup (once; no device memory involved)
    static cudaStream_t sB = nullptr;
    static cudaEvent_t  eC = nullptr, eF = nullptr, eJ = nullptr;
    if (sB == nullptr) {
        cudaStreamCreateWithFlags(&sB, cudaStreamNonBlocking);
        cudaEventCreateWithFlags(&eC, cudaEventDisableTiming);
        cudaEventCreateWithFlags(&eF, cudaEventDisableTiming);
        cudaEventCreateWithFlags(&eJ, cudaEventDisableTiming);
        cudaFuncSetAttribute(gemm_mma_kernel<DIN>,
                             cudaFuncAttributeMaxDynamicSharedMemorySize,
                             (128 + 64) * (DIN + 8) * 2);
        cudaFuncSetAttribute(gemm_mma_kernel<HH>,
                             cudaFuncAttributeMaxDynamicSharedMemorySize,
                             (128 + 64) * (HH + 8) * 2);
    }
    const int SMEM1 = (128 + 64) * (DIN + 8) * 2;   // 52224 (K=128)
    const int SMEM2 = (128 + 64) * (HH + 8) * 2;    // 27648 (K=64)

    const int NB_I  = (CAP / 4 + 255) / 256;        // 977
    const int NB_N  = (NN + 255) / 256;             // 196
    const int NB_E4 = (EE / 4 + 255) / 256;         // 782
    const int NB_X  = (NN * DIN / 4 + 255) / 256;   // 6250

    // fork side stream: fp16 conversions run under the CSR build
    cudaEventRecord(eC, 0);
    cudaStreamWaitEvent(sB, eC, 0);
    xconv_kernel<<<NB_X, 256, 0, sB>>>(x);
    wconv_kernel<<<(DIN * HH + 2 * HH * HH + 255) / 256, 256, 0, sB>>>(W1, W2, W3);

    // CSR build on the main stream
    init_kernel<<<NB_I, 256>>>();
    count_kernel<<<NB_E4, 256>>>(ei);
    alloc_kernel<<<NB_N, 256>>>();

    // GEMM1 (needs dinv + converted x) on sB, concurrent with scatter
    cudaEventRecord(eF, 0);
    cudaStreamWaitEvent(sB, eF, 0);
    gemm_mma_kernel<DIN><<<GTB, 128, SMEM1, sB>>>(xh, w1t, NN);
    cudaEventRecord(eJ, sB);

    scatter_kernel<<<NB_E4, 256>>>(ei);

    // join: agg1 needs both CSR and GEMM1
    cudaStreamWaitEvent(0, eJ, 0);

    agg_kernel<<<AB, 256>>>(b1);
    gemm_mma_kernel<HH><<<GTB, 128, SMEM2>>>(hAH, w2t, NN);
    agg_kernel<<<AB, 256>>>(b2);
    gemm_mma_kernel<HH><<<GTB, 128, SMEM2>>>(hAH, w3t, NN);
    agg_pool_kernel<<<AB, 256>>>(b3);

    pool_reduce_kernel<<<32, 256>>>();
    head_kernel<<<1, 64>>>(fw1, fb1, fw2, fb2, out);
}